// round 2
// baseline (speedup 1.0000x reference)
#include <cuda_runtime.h>

// ---------------------------------------------------------------------------
// GCN: out = blockdiag(adj, 64x) @ (x @ W)
//   GEMM1: H[32768,256] = X[32768,256] @ W[256,256]
//   GEMM2: Out[b][512,256] = adj[512,512] @ H[b][512,256], b = 0..63
// fp32 row-major. Inner product via packed fma.rn.f32x2 (FFMA2): 2 FMA / issue.
// ---------------------------------------------------------------------------

#define BM 128
#define BN 128
#define BK 16
#define TM 8
#define TN 8
#define NTHREADS 256   // (BM/TM)*(BN/TN)

// Scratch for intermediate H = X @ W  (32768 x 256 fp32 = 32 MB)
__device__ float g_h[32768 * 256];

__device__ __forceinline__ unsigned long long pack2(float lo, float hi) {
    unsigned long long r;
    asm("mov.b64 %0, {%1, %2};" : "=l"(r) : "f"(lo), "f"(hi));
    return r;
}

__device__ __forceinline__ void ffma2(unsigned long long& d,
                                      unsigned long long a,
                                      unsigned long long b) {
    asm("fma.rn.f32x2 %0, %1, %2, %3;" : "=l"(d) : "l"(a), "l"(b), "l"(d));
}

__device__ __forceinline__ float2 unpack2(unsigned long long v) {
    float2 f;
    asm("mov.b64 {%0, %1}, %2;" : "=f"(f.x), "=f"(f.y) : "l"(v));
    return f;
}

__global__ __launch_bounds__(NTHREADS, 2)
void sgemm_f32x2(const float* __restrict__ A,
                 const float* __restrict__ B,
                 float* __restrict__ C,
                 int M, int N, int K,
                 long aBatchStride, long bBatchStride, long cBatchStride) {
    A += (long)blockIdx.z * aBatchStride;
    B += (long)blockIdx.z * bBatchStride;
    C += (long)blockIdx.z * cBatchStride;

    __shared__ float As[BK][BM];   // A tile, transposed (k-major rows)
    __shared__ float Bs[BK][BN];

    const int tid  = threadIdx.x;
    const int tcol = tid % (BN / TN);   // 0..15
    const int trow = tid / (BN / TN);   // 0..15

    // A-tile load mapping: BM x BK floats = 512 float4, 2 per thread
    const int aRow  = tid / (BK / 4);   // 0..63  (then +64)
    const int aCol4 = tid % (BK / 4);   // 0..3
    // B-tile load mapping: BK x BN floats = 512 float4, 2 per thread
    const int bRow  = tid / (BN / 4);   // 0..7   (then +8)
    const int bCol4 = tid % (BN / 4);   // 0..31

    const float* Aptr = A + (long)(blockIdx.y * BM) * K;
    const float* Bptr = B + blockIdx.x * BN;

    // acc2[i][jp] holds packed pair (C[i][2jp], C[i][2jp+1])
    unsigned long long acc2[TM][TN / 2];
#pragma unroll
    for (int i = 0; i < TM; i++)
#pragma unroll
        for (int jp = 0; jp < TN / 2; jp++) acc2[i][jp] = 0ull;

    for (int k0 = 0; k0 < K; k0 += BK) {
        // Load A tile (transpose into As[k][m])
#pragma unroll
        for (int it = 0; it < 2; it++) {
            int r = aRow + it * 64;
            float4 v = *(const float4*)(Aptr + (long)r * K + k0 + aCol4 * 4);
            As[aCol4 * 4 + 0][r] = v.x;
            As[aCol4 * 4 + 1][r] = v.y;
            As[aCol4 * 4 + 2][r] = v.z;
            As[aCol4 * 4 + 3][r] = v.w;
        }
        // Load B tile (direct)
#pragma unroll
        for (int it = 0; it < 2; it++) {
            int r = bRow + it * 8;
            *(float4*)(&Bs[r][bCol4 * 4]) =
                *(const float4*)(Bptr + (long)(k0 + r) * N + bCol4 * 4);
        }
        __syncthreads();

#pragma unroll
        for (int k = 0; k < BK; k++) {
            float4 m0 = *(const float4*)(&As[k][trow * TM]);
            float4 m1 = *(const float4*)(&As[k][trow * TM + 4]);
            float4 n0 = *(const float4*)(&Bs[k][tcol * TN]);
            float4 n1 = *(const float4*)(&Bs[k][tcol * TN + 4]);

            unsigned long long nn[TN / 2];
            nn[0] = pack2(n0.x, n0.y);
            nn[1] = pack2(n0.z, n0.w);
            nn[2] = pack2(n1.x, n1.y);
            nn[3] = pack2(n1.z, n1.w);

            unsigned long long mm[TM];
            mm[0] = pack2(m0.x, m0.x);
            mm[1] = pack2(m0.y, m0.y);
            mm[2] = pack2(m0.z, m0.z);
            mm[3] = pack2(m0.w, m0.w);
            mm[4] = pack2(m1.x, m1.x);
            mm[5] = pack2(m1.y, m1.y);
            mm[6] = pack2(m1.z, m1.z);
            mm[7] = pack2(m1.w, m1.w);

#pragma unroll
            for (int i = 0; i < TM; i++)
#pragma unroll
                for (int jp = 0; jp < TN / 2; jp++)
                    ffma2(acc2[i][jp], mm[i], nn[jp]);
        }
        __syncthreads();
    }

    float* Cptr = C + (long)(blockIdx.y * BM + trow * TM) * N + blockIdx.x * BN + tcol * TN;
#pragma unroll
    for (int i = 0; i < TM; i++) {
        float2 p0 = unpack2(acc2[i][0]);
        float2 p1 = unpack2(acc2[i][1]);
        float2 p2 = unpack2(acc2[i][2]);
        float2 p3 = unpack2(acc2[i][3]);
        float4 v0 = {p0.x, p0.y, p1.x, p1.y};
        float4 v1 = {p2.x, p2.y, p3.x, p3.y};
        *(float4*)(Cptr + (long)i * N + 0) = v0;
        *(float4*)(Cptr + (long)i * N + 4) = v1;
    }
}

extern "C" void kernel_launch(void* const* d_in, const int* in_sizes, int n_in,
                              void* d_out, int out_size) {
    const float* x      = (const float*)d_in[0];   // [32768, 256]
    // d_in[1] = batch (int64) — contiguous blocks, unused
    const float* weight = (const float*)d_in[2];   // [256, 256]
    const float* adj    = (const float*)d_in[3];   // [512, 512]
    float* out          = (float*)d_out;           // [32768, 256]

    const int N_NODES = 512;
    const int N_BATCH = 64;
    const int D_IN    = 256;
    const int D_OUT   = 256;
    const int M1      = N_NODES * N_BATCH;         // 32768

    float* h;
    cudaGetSymbolAddress((void**)&h, g_h);

    // GEMM1: H = X @ W   (M=32768, N=256, K=256)
    {
        dim3 grid(D_OUT / BN, M1 / BM, 1);
        sgemm_f32x2<<<grid, NTHREADS>>>(x, weight, h,
                                        M1, D_OUT, D_IN,
                                        0L, 0L, 0L);
    }
    // GEMM2: Out[b] = adj @ H[b]   (M=512, N=256, K=512), batched over 64
    {
        dim3 grid(D_OUT / BN, N_NODES / BM, N_BATCH);
        sgemm_f32x2<<<grid, NTHREADS>>>(adj, h, out,
                                        N_NODES, D_OUT, N_NODES,
                                        0L, (long)N_NODES * D_OUT, (long)N_NODES * D_OUT);
    }
}

// round 4
// speedup vs baseline: 1.9855x; 1.9855x over previous
#include <cuda_runtime.h>
#include <cuda_bf16.h>
#include <cstdint>

// ---------------------------------------------------------------------------
// GCN via mma.sync bf16 split-fp32 GEMMs (tcgen05 unavailable: ptxas target
// is plain sm_103).
//   GEMM1: H^T[256][32768] = W^T @ X^T  (A=W^T K-major, B=X K-major) -> bf16 hi/lo
//   GEMM2: Out[b] = adj @ H_b           (A=adj K-major, B=H^T K-major) -> fp32
// fp32 emulated as 3 bf16 MMAs: ahi*bhi + ahi*blo + alo*bhi.
// ---------------------------------------------------------------------------

#define N_NODES 512
#define N_BATCH 64
#define D_IN    256
#define D_OUT   256
#define M_ALL   (N_NODES * N_BATCH)   // 32768

#define BM 128
#define BN 128
#define BKB 32                      // bf16 k per stage
#define NTHREADS 256
#define PITCH 40                    // smem row pitch in bf16 (80 bytes)
#define TILE_BYTES (BM * PITCH * 2) // 10240 per (matrix, split)
#define STAGE_BYTES (4 * TILE_BYTES)
#define SMEM_TOTAL (2 * STAGE_BYTES)
#define OFF_AH 0
#define OFF_AL TILE_BYTES
#define OFF_BH (2 * TILE_BYTES)
#define OFF_BL (3 * TILE_BYTES)

// device scratch
__device__ __nv_bfloat16 g_xhi[M_ALL * D_IN];
__device__ __nv_bfloat16 g_xlo[M_ALL * D_IN];
__device__ __nv_bfloat16 g_wthi[D_OUT * D_IN];
__device__ __nv_bfloat16 g_wtlo[D_OUT * D_IN];
__device__ __nv_bfloat16 g_ahi[N_NODES * N_NODES];
__device__ __nv_bfloat16 g_alo[N_NODES * N_NODES];
__device__ __nv_bfloat16 g_hhi[(size_t)D_OUT * M_ALL];
__device__ __nv_bfloat16 g_hlo[(size_t)D_OUT * M_ALL];

// ---------------- helpers ----------------
__device__ __forceinline__ uint32_t smem_u32(const void* p) {
    uint32_t a;
    asm("{ .reg .u64 t; cvta.to.shared.u64 t, %1; cvt.u32.u64 %0, t; }" : "=r"(a) : "l"(p));
    return a;
}
__device__ __forceinline__ void ldsm_x4(uint32_t* r, uint32_t addr) {
    asm volatile("ldmatrix.sync.aligned.m8n8.x4.shared.b16 {%0,%1,%2,%3}, [%4];"
                 : "=r"(r[0]), "=r"(r[1]), "=r"(r[2]), "=r"(r[3]) : "r"(addr));
}
__device__ __forceinline__ void mma_bf16(float* c, const uint32_t* a, const uint32_t* b) {
    asm volatile(
        "mma.sync.aligned.m16n8k16.row.col.f32.bf16.bf16.f32 "
        "{%0,%1,%2,%3}, {%4,%5,%6,%7}, {%8,%9}, {%0,%1,%2,%3};"
        : "+f"(c[0]), "+f"(c[1]), "+f"(c[2]), "+f"(c[3])
        : "r"(a[0]), "r"(a[1]), "r"(a[2]), "r"(a[3]), "r"(b[0]), "r"(b[1]));
}
__device__ __forceinline__ void split1(float v, __nv_bfloat16& h, __nv_bfloat16& l) {
    h = __float2bfloat16(v);
    l = __float2bfloat16(v - __bfloat162float(h));
}
__device__ __forceinline__ uint32_t packbf(__nv_bfloat16 a, __nv_bfloat16 b) {
    return (uint32_t)__bfloat16_as_ushort(a) | ((uint32_t)__bfloat16_as_ushort(b) << 16);
}

// ---------------- split kernels ----------------
__global__ __launch_bounds__(256) void split8(const float* __restrict__ in,
                                              __nv_bfloat16* __restrict__ hi,
                                              __nv_bfloat16* __restrict__ lo, int n8) {
    int i = blockIdx.x * blockDim.x + threadIdx.x;
    int stride = gridDim.x * blockDim.x;
    for (; i < n8; i += stride) {
        float4 a = ((const float4*)in)[2 * i];
        float4 b = ((const float4*)in)[2 * i + 1];
        float f[8] = {a.x, a.y, a.z, a.w, b.x, b.y, b.z, b.w};
        __nv_bfloat16 h[8], l[8];
#pragma unroll
        for (int j = 0; j < 8; j++) split1(f[j], h[j], l[j]);
        uint4 vh = {packbf(h[0], h[1]), packbf(h[2], h[3]), packbf(h[4], h[5]), packbf(h[6], h[7])};
        uint4 vl = {packbf(l[0], l[1]), packbf(l[2], l[3]), packbf(l[4], l[5]), packbf(l[6], l[7])};
        ((uint4*)hi)[i] = vh;
        ((uint4*)lo)[i] = vl;
    }
}

__global__ __launch_bounds__(256) void split_wt(const float* __restrict__ w,
                                                __nv_bfloat16* __restrict__ thi,
                                                __nv_bfloat16* __restrict__ tlo) {
    int o = blockIdx.x;
    int i = threadIdx.x;
    float v = w[i * D_OUT + o];
    __nv_bfloat16 h, l;
    split1(v, h, l);
    thi[o * D_IN + i] = h;
    tlo[o * D_IN + i] = l;
}

// ---------------- main GEMM: C = A * B^T (both K-major) ----------------
template <bool SPLIT_OUT>
__global__ __launch_bounds__(NTHREADS)
void hgemm_split(const __nv_bfloat16* __restrict__ Ahi, const __nv_bfloat16* __restrict__ Alo,
                 int lda,
                 const __nv_bfloat16* __restrict__ Bhi, const __nv_bfloat16* __restrict__ Blo,
                 int ldb, long bStride,
                 __nv_bfloat16* __restrict__ Chi, __nv_bfloat16* __restrict__ Clo,
                 float* __restrict__ Cf, int ldc, long cStride,
                 int K) {
    extern __shared__ char smem[];
    const uint32_t sb = smem_u32(smem);
    const int tid = threadIdx.x;
    const int lane = tid & 31;
    const int wid = tid >> 5;
    const int wm = (wid & 3) * 32;   // warp m offset in tile
    const int wn = (wid >> 2) * 64;  // warp n offset in tile

    const int m0 = blockIdx.y * BM;
    const int n0 = blockIdx.x * BN;
    const long bz = blockIdx.z;
    Bhi += bz * bStride;
    Blo += bz * bStride;

    // per-thread global load coords: 2 uint4 per split per matrix
    const int lr = tid >> 2;        // 0..63 (then +64)
    const int lc = (tid & 3) * 8;   // bf16 column within BK

    // ldmatrix base addresses (per warp)
    const uint32_t aOff = (uint32_t)((wm + (lane & 15)) * (PITCH * 2) + ((lane >> 4) << 4));
    const uint32_t bOff = (uint32_t)((wn + ((lane >> 4) << 3) + (lane & 7)) * (PITCH * 2) +
                                     (((lane >> 3) & 1) << 4));

    float acc[2][8][4];
#pragma unroll
    for (int mt = 0; mt < 2; mt++)
#pragma unroll
        for (int nt = 0; nt < 8; nt++)
#pragma unroll
            for (int q = 0; q < 4; q++) acc[mt][nt][q] = 0.0f;

    const int NT = K / BKB;
    uint4 av[2][2], bv[2][2];

    // prologue: load stage 0
#pragma unroll
    for (int j = 0; j < 2; j++) {
        int r = lr + j * 64;
        av[j][0] = *(const uint4*)(Ahi + (size_t)(m0 + r) * lda + lc);
        av[j][1] = *(const uint4*)(Alo + (size_t)(m0 + r) * lda + lc);
        bv[j][0] = *(const uint4*)(Bhi + (size_t)(n0 + r) * ldb + lc);
        bv[j][1] = *(const uint4*)(Blo + (size_t)(n0 + r) * ldb + lc);
    }
#pragma unroll
    for (int j = 0; j < 2; j++) {
        int r = lr + j * 64;
        uint32_t so = (uint32_t)(r * (PITCH * 2) + (tid & 3) * 16);
        *(uint4*)(smem + OFF_AH + so) = av[j][0];
        *(uint4*)(smem + OFF_AL + so) = av[j][1];
        *(uint4*)(smem + OFF_BH + so) = bv[j][0];
        *(uint4*)(smem + OFF_BL + so) = bv[j][1];
    }
    __syncthreads();

    for (int t = 0; t < NT; t++) {
        // issue loads for next stage
        if (t + 1 < NT) {
            int k0 = (t + 1) * BKB + lc;
#pragma unroll
            for (int j = 0; j < 2; j++) {
                int r = lr + j * 64;
                av[j][0] = *(const uint4*)(Ahi + (size_t)(m0 + r) * lda + k0);
                av[j][1] = *(const uint4*)(Alo + (size_t)(m0 + r) * lda + k0);
                bv[j][0] = *(const uint4*)(Bhi + (size_t)(n0 + r) * ldb + k0);
                bv[j][1] = *(const uint4*)(Blo + (size_t)(n0 + r) * ldb + k0);
            }
        }

        // compute on stage t
        const uint32_t st = sb + (uint32_t)((t & 1) * STAGE_BYTES);
#pragma unroll
        for (int ko = 0; ko < 2; ko++) {
            uint32_t ah[2][4], al[2][4];
#pragma unroll
            for (int mt = 0; mt < 2; mt++) {
                ldsm_x4(ah[mt], st + OFF_AH + aOff + mt * 16 * (PITCH * 2) + ko * 32);
                ldsm_x4(al[mt], st + OFF_AL + aOff + mt * 16 * (PITCH * 2) + ko * 32);
            }
#pragma unroll
            for (int np = 0; np < 4; np++) {
                uint32_t bh[4], bl[4];
                ldsm_x4(bh, st + OFF_BH + bOff + np * 16 * (PITCH * 2) + ko * 32);
                ldsm_x4(bl, st + OFF_BL + bOff + np * 16 * (PITCH * 2) + ko * 32);
#pragma unroll
                for (int sub = 0; sub < 2; sub++) {
                    int nt = np * 2 + sub;
#pragma unroll
                    for (int mt = 0; mt < 2; mt++) {
                        mma_bf16(acc[mt][nt], ah[mt], bh + sub * 2);
                        mma_bf16(acc[mt][nt], ah[mt], bl + sub * 2);
                        mma_bf16(acc[mt][nt], al[mt], bh + sub * 2);
                    }
                }
            }
        }

        // store next stage
        if (t + 1 < NT) {
            char* dst = smem + ((t + 1) & 1) * STAGE_BYTES;
#pragma unroll
            for (int j = 0; j < 2; j++) {
                int r = lr + j * 64;
                uint32_t so = (uint32_t)(r * (PITCH * 2) + (tid & 3) * 16);
                *(uint4*)(dst + OFF_AH + so) = av[j][0];
                *(uint4*)(dst + OFF_AL + so) = av[j][1];
                *(uint4*)(dst + OFF_BH + so) = bv[j][0];
                *(uint4*)(dst + OFF_BL + so) = bv[j][1];
            }
        }
        __syncthreads();
    }

    // epilogue
    const int l4 = lane >> 2;
    const int lp = lane & 3;
#pragma unroll
    for (int mt = 0; mt < 2; mt++) {
#pragma unroll
        for (int nt = 0; nt < 8; nt++) {
            const float* c = acc[mt][nt];
            long m = m0 + wm + mt * 16 + l4;
            long n = n0 + wn + nt * 8 + lp * 2;
            if (SPLIT_OUT) {
                __nv_bfloat16 h0, l0, h1, l1;
                split1(c[0], h0, l0);
                split1(c[1], h1, l1);
                *(uint32_t*)(Chi + m * ldc + n) = packbf(h0, h1);
                *(uint32_t*)(Clo + m * ldc + n) = packbf(l0, l1);
                split1(c[2], h0, l0);
                split1(c[3], h1, l1);
                *(uint32_t*)(Chi + (m + 8) * ldc + n) = packbf(h0, h1);
                *(uint32_t*)(Clo + (m + 8) * ldc + n) = packbf(l0, l1);
            } else {
                float* base = Cf + bz * cStride;
                *(float2*)(base + m * ldc + n) = make_float2(c[0], c[1]);
                *(float2*)(base + (m + 8) * ldc + n) = make_float2(c[2], c[3]);
            }
        }
    }
}

// ---------------- launch ----------------
extern "C" void kernel_launch(void* const* d_in, const int* in_sizes, int n_in,
                              void* d_out, int out_size) {
    const float* x      = (const float*)d_in[0];
    const float* weight = (const float*)d_in[2];
    const float* adj    = (const float*)d_in[3];
    float* out          = (float*)d_out;

    __nv_bfloat16 *xhi, *xlo, *wthi, *wtlo, *ahi, *alo, *hhi, *hlo;
    cudaGetSymbolAddress((void**)&xhi, g_xhi);
    cudaGetSymbolAddress((void**)&xlo, g_xlo);
    cudaGetSymbolAddress((void**)&wthi, g_wthi);
    cudaGetSymbolAddress((void**)&wtlo, g_wtlo);
    cudaGetSymbolAddress((void**)&ahi, g_ahi);
    cudaGetSymbolAddress((void**)&alo, g_alo);
    cudaGetSymbolAddress((void**)&hhi, g_hhi);
    cudaGetSymbolAddress((void**)&hlo, g_hlo);

    cudaFuncSetAttribute(hgemm_split<true>, cudaFuncAttributeMaxDynamicSharedMemorySize, SMEM_TOTAL);
    cudaFuncSetAttribute(hgemm_split<false>, cudaFuncAttributeMaxDynamicSharedMemorySize, SMEM_TOTAL);

    // splits
    split8<<<1024, 256>>>(x, xhi, xlo, M_ALL * D_IN / 8);
    split8<<<128, 256>>>(adj, ahi, alo, N_NODES * N_NODES / 8);
    split_wt<<<D_OUT, 256>>>(weight, wthi, wtlo);

    // GEMM1: H^T = W^T @ X^T ; A=W^T [256][256], B=X [32768][256]
    {
        dim3 grid(M_ALL / BN, D_OUT / BM, 1);
        hgemm_split<true><<<grid, NTHREADS, SMEM_TOTAL>>>(
            wthi, wtlo, D_IN,
            xhi, xlo, D_IN, 0L,
            hhi, hlo, nullptr, M_ALL, 0L,
            D_IN);
    }
    // GEMM2: Out[b] = adj @ H_b ; A=adj [512][512], B=H^T [256][32768] col-slice b*512
    {
        dim3 grid(D_OUT / BN, N_NODES / BM, N_BATCH);
        hgemm_split<false><<<grid, NTHREADS, SMEM_TOTAL>>>(
            ahi, alo, N_NODES,
            hhi, hlo, M_ALL, (long)N_NODES,
            nullptr, nullptr, out, D_OUT, (long)(N_NODES * D_OUT),
            N_NODES);
    }
}

// round 5
// speedup vs baseline: 2.2021x; 1.1091x over previous
#include <cuda_runtime.h>
#include <cuda_bf16.h>
#include <cstdint>

// ---------------------------------------------------------------------------
// GCN via mma.sync bf16 split-fp32 GEMMs (tcgen05 unavailable on sm_103 target).
//   GEMM1: H^T[256][32768] = W^T @ X^T  (A=W^T K-major, B=X K-major) -> bf16 hi/lo
//   GEMM2: Out[b] = adj @ H_b           (A=adj K-major, B=H^T K-major) -> fp32
// fp32 emulated as 3 bf16 MMAs: ahi*bhi + ahi*blo + alo*bhi.
// R5: cp.async loads + __launch_bounds__(256,2) for 2 CTAs/SM.
// ---------------------------------------------------------------------------

#define N_NODES 512
#define N_BATCH 64
#define D_IN    256
#define D_OUT   256
#define M_ALL   (N_NODES * N_BATCH)   // 32768

#define BM 128
#define BN 128
#define BKB 32                      // bf16 k per stage
#define NTHREADS 256
#define PITCH 40                    // smem row pitch in bf16 (80 bytes)
#define TILE_BYTES (BM * PITCH * 2) // 10240 per (matrix, split)
#define STAGE_BYTES (4 * TILE_BYTES)
#define SMEM_TOTAL (2 * STAGE_BYTES)
#define OFF_AH 0
#define OFF_AL TILE_BYTES
#define OFF_BH (2 * TILE_BYTES)
#define OFF_BL (3 * TILE_BYTES)

// device scratch
__device__ __nv_bfloat16 g_xhi[M_ALL * D_IN];
__device__ __nv_bfloat16 g_xlo[M_ALL * D_IN];
__device__ __nv_bfloat16 g_wthi[D_OUT * D_IN];
__device__ __nv_bfloat16 g_wtlo[D_OUT * D_IN];
__device__ __nv_bfloat16 g_ahi[N_NODES * N_NODES];
__device__ __nv_bfloat16 g_alo[N_NODES * N_NODES];
__device__ __nv_bfloat16 g_hhi[(size_t)D_OUT * M_ALL];
__device__ __nv_bfloat16 g_hlo[(size_t)D_OUT * M_ALL];

// ---------------- helpers ----------------
__device__ __forceinline__ uint32_t smem_u32(const void* p) {
    uint32_t a;
    asm("{ .reg .u64 t; cvta.to.shared.u64 t, %1; cvt.u32.u64 %0, t; }" : "=r"(a) : "l"(p));
    return a;
}
__device__ __forceinline__ void cp16(uint32_t dst, const void* src) {
    asm volatile("cp.async.cg.shared.global [%0], [%1], 16;" :: "r"(dst), "l"(src) : "memory");
}
__device__ __forceinline__ void cp_commit() {
    asm volatile("cp.async.commit_group;" ::: "memory");
}
template <int N>
__device__ __forceinline__ void cp_wait() {
    asm volatile("cp.async.wait_group %0;" :: "n"(N) : "memory");
}
__device__ __forceinline__ void ldsm_x4(uint32_t* r, uint32_t addr) {
    asm volatile("ldmatrix.sync.aligned.m8n8.x4.shared.b16 {%0,%1,%2,%3}, [%4];"
                 : "=r"(r[0]), "=r"(r[1]), "=r"(r[2]), "=r"(r[3]) : "r"(addr));
}
__device__ __forceinline__ void mma_bf16(float* c, const uint32_t* a, const uint32_t* b) {
    asm volatile(
        "mma.sync.aligned.m16n8k16.row.col.f32.bf16.bf16.f32 "
        "{%0,%1,%2,%3}, {%4,%5,%6,%7}, {%8,%9}, {%0,%1,%2,%3};"
        : "+f"(c[0]), "+f"(c[1]), "+f"(c[2]), "+f"(c[3])
        : "r"(a[0]), "r"(a[1]), "r"(a[2]), "r"(a[3]), "r"(b[0]), "r"(b[1]));
}
__device__ __forceinline__ void split1(float v, __nv_bfloat16& h, __nv_bfloat16& l) {
    h = __float2bfloat16(v);
    l = __float2bfloat16(v - __bfloat162float(h));
}
__device__ __forceinline__ uint32_t packbf(__nv_bfloat16 a, __nv_bfloat16 b) {
    return (uint32_t)__bfloat16_as_ushort(a) | ((uint32_t)__bfloat16_as_ushort(b) << 16);
}

// ---------------- split kernels ----------------
__global__ __launch_bounds__(256) void split8(const float* __restrict__ in,
                                              __nv_bfloat16* __restrict__ hi,
                                              __nv_bfloat16* __restrict__ lo, int n8) {
    int i = blockIdx.x * blockDim.x + threadIdx.x;
    int stride = gridDim.x * blockDim.x;
    for (; i < n8; i += stride) {
        float4 a = ((const float4*)in)[2 * i];
        float4 b = ((const float4*)in)[2 * i + 1];
        float f[8] = {a.x, a.y, a.z, a.w, b.x, b.y, b.z, b.w};
        __nv_bfloat16 h[8], l[8];
#pragma unroll
        for (int j = 0; j < 8; j++) split1(f[j], h[j], l[j]);
        uint4 vh = {packbf(h[0], h[1]), packbf(h[2], h[3]), packbf(h[4], h[5]), packbf(h[6], h[7])};
        uint4 vl = {packbf(l[0], l[1]), packbf(l[2], l[3]), packbf(l[4], l[5]), packbf(l[6], l[7])};
        ((uint4*)hi)[i] = vh;
        ((uint4*)lo)[i] = vl;
    }
}

__global__ __launch_bounds__(256) void split_wt(const float* __restrict__ w,
                                                __nv_bfloat16* __restrict__ thi,
                                                __nv_bfloat16* __restrict__ tlo) {
    int o = blockIdx.x;
    int i = threadIdx.x;
    float v = w[i * D_OUT + o];
    __nv_bfloat16 h, l;
    split1(v, h, l);
    thi[o * D_IN + i] = h;
    tlo[o * D_IN + i] = l;
}

// ---------------- main GEMM: C = A * B^T (both K-major) ----------------
template <bool SPLIT_OUT>
__global__ __launch_bounds__(NTHREADS, 2)
void hgemm_split(const __nv_bfloat16* __restrict__ Ahi, const __nv_bfloat16* __restrict__ Alo,
                 int lda,
                 const __nv_bfloat16* __restrict__ Bhi, const __nv_bfloat16* __restrict__ Blo,
                 int ldb, long bStride,
                 __nv_bfloat16* __restrict__ Chi, __nv_bfloat16* __restrict__ Clo,
                 float* __restrict__ Cf, int ldc, long cStride,
                 int K) {
    extern __shared__ char smem[];
    const uint32_t sb = smem_u32(smem);
    const int tid = threadIdx.x;
    const int lane = tid & 31;
    const int wid = tid >> 5;
    const int wm = (wid & 3) * 32;   // warp m offset in tile
    const int wn = (wid >> 2) * 64;  // warp n offset in tile

    const int m0 = blockIdx.y * BM;
    const int n0 = blockIdx.x * BN;
    const long bz = blockIdx.z;
    Bhi += bz * bStride;
    Blo += bz * bStride;

    // per-thread cp.async coords: rows lr, lr+64; 16B at bf16 col lc
    const int lr = tid >> 2;        // 0..63
    const int lc = (tid & 3) * 8;   // bf16 column within BK
    const uint32_t soBase = (uint32_t)((tid & 3) * 16);

    // ldmatrix base addresses (per warp)
    const uint32_t aOff = (uint32_t)((wm + (lane & 15)) * (PITCH * 2) + ((lane >> 4) << 4));
    const uint32_t bOff = (uint32_t)((wn + ((lane >> 4) << 3) + (lane & 7)) * (PITCH * 2) +
                                     (((lane >> 3) & 1) << 4));

    float acc[2][8][4];
#pragma unroll
    for (int mt = 0; mt < 2; mt++)
#pragma unroll
        for (int nt = 0; nt < 8; nt++)
#pragma unroll
            for (int q = 0; q < 4; q++) acc[mt][nt][q] = 0.0f;

    const int NT = K / BKB;

    // async load of one stage
    auto load_stage = [&](int t) {
        const uint32_t st = sb + (uint32_t)((t & 1) * STAGE_BYTES);
        const int k0 = t * BKB + lc;
#pragma unroll
        for (int j = 0; j < 2; j++) {
            int r = lr + j * 64;
            uint32_t so = (uint32_t)(r * (PITCH * 2)) + soBase;
            cp16(st + OFF_AH + so, Ahi + (size_t)(m0 + r) * lda + k0);
            cp16(st + OFF_AL + so, Alo + (size_t)(m0 + r) * lda + k0);
            cp16(st + OFF_BH + so, Bhi + (size_t)(n0 + r) * ldb + k0);
            cp16(st + OFF_BL + so, Blo + (size_t)(n0 + r) * ldb + k0);
        }
        cp_commit();
    };

    load_stage(0);
    if (NT > 1) load_stage(1);
    cp_wait<1>();
    __syncthreads();

    for (int t = 0; t < NT; t++) {
        // compute on stage t
        const uint32_t st = sb + (uint32_t)((t & 1) * STAGE_BYTES);
#pragma unroll
        for (int ko = 0; ko < 2; ko++) {
            uint32_t ah[2][4], al[2][4];
#pragma unroll
            for (int mt = 0; mt < 2; mt++) {
                ldsm_x4(ah[mt], st + OFF_AH + aOff + mt * 16 * (PITCH * 2) + ko * 32);
                ldsm_x4(al[mt], st + OFF_AL + aOff + mt * 16 * (PITCH * 2) + ko * 32);
            }
#pragma unroll
            for (int np = 0; np < 4; np++) {
                uint32_t bh[4], bl[4];
                ldsm_x4(bh, st + OFF_BH + bOff + np * 16 * (PITCH * 2) + ko * 32);
                ldsm_x4(bl, st + OFF_BL + bOff + np * 16 * (PITCH * 2) + ko * 32);
#pragma unroll
                for (int sub = 0; sub < 2; sub++) {
                    int nt = np * 2 + sub;
#pragma unroll
                    for (int mt = 0; mt < 2; mt++) {
                        mma_bf16(acc[mt][nt], ah[mt], bh + sub * 2);
                        mma_bf16(acc[mt][nt], ah[mt], bl + sub * 2);
                        mma_bf16(acc[mt][nt], al[mt], bh + sub * 2);
                    }
                }
            }
        }

        // issue loads for stage t+2, then wait for stage t+1
        __syncthreads();
        if (t + 2 < NT) {
            load_stage(t + 2);
            cp_wait<1>();
        } else {
            cp_wait<0>();
        }
        __syncthreads();
    }

    // epilogue
    const int l4 = lane >> 2;
    const int lp = lane & 3;
#pragma unroll
    for (int mt = 0; mt < 2; mt++) {
#pragma unroll
        for (int nt = 0; nt < 8; nt++) {
            const float* c = acc[mt][nt];
            long m = m0 + wm + mt * 16 + l4;
            long n = n0 + wn + nt * 8 + lp * 2;
            if (SPLIT_OUT) {
                __nv_bfloat16 h0, l0, h1, l1;
                split1(c[0], h0, l0);
                split1(c[1], h1, l1);
                *(uint32_t*)(Chi + m * ldc + n) = packbf(h0, h1);
                *(uint32_t*)(Clo + m * ldc + n) = packbf(l0, l1);
                split1(c[2], h0, l0);
                split1(c[3], h1, l1);
                *(uint32_t*)(Chi + (m + 8) * ldc + n) = packbf(h0, h1);
                *(uint32_t*)(Clo + (m + 8) * ldc + n) = packbf(l0, l1);
            } else {
                float* base = Cf + bz * cStride;
                *(float2*)(base + m * ldc + n) = make_float2(c[0], c[1]);
                *(float2*)(base + (m + 8) * ldc + n) = make_float2(c[2], c[3]);
            }
        }
    }
}

// ---------------- launch ----------------
extern "C" void kernel_launch(void* const* d_in, const int* in_sizes, int n_in,
                              void* d_out, int out_size) {
    const float* x      = (const float*)d_in[0];
    const float* weight = (const float*)d_in[2];
    const float* adj    = (const float*)d_in[3];
    float* out          = (float*)d_out;

    __nv_bfloat16 *xhi, *xlo, *wthi, *wtlo, *ahi, *alo, *hhi, *hlo;
    cudaGetSymbolAddress((void**)&xhi, g_xhi);
    cudaGetSymbolAddress((void**)&xlo, g_xlo);
    cudaGetSymbolAddress((void**)&wthi, g_wthi);
    cudaGetSymbolAddress((void**)&wtlo, g_wtlo);
    cudaGetSymbolAddress((void**)&ahi, g_ahi);
    cudaGetSymbolAddress((void**)&alo, g_alo);
    cudaGetSymbolAddress((void**)&hhi, g_hhi);
    cudaGetSymbolAddress((void**)&hlo, g_hlo);

    cudaFuncSetAttribute(hgemm_split<true>, cudaFuncAttributeMaxDynamicSharedMemorySize, SMEM_TOTAL);
    cudaFuncSetAttribute(hgemm_split<false>, cudaFuncAttributeMaxDynamicSharedMemorySize, SMEM_TOTAL);

    // splits
    split8<<<1024, 256>>>(x, xhi, xlo, M_ALL * D_IN / 8);
    split8<<<128, 256>>>(adj, ahi, alo, N_NODES * N_NODES / 8);
    split_wt<<<D_OUT, 256>>>(weight, wthi, wtlo);

    // GEMM1: H^T = W^T @ X^T ; A=W^T [256][256], B=X [32768][256]
    {
        dim3 grid(M_ALL / BN, D_OUT / BM, 1);
        hgemm_split<true><<<grid, NTHREADS, SMEM_TOTAL>>>(
            wthi, wtlo, D_IN,
            xhi, xlo, D_IN, 0L,
            hhi, hlo, nullptr, M_ALL, 0L,
            D_IN);
    }
    // GEMM2: Out[b] = adj @ H_b ; A=adj [512][512], B=H^T [256][32768] col-slice b*512
    {
        dim3 grid(D_OUT / BN, N_NODES / BM, N_BATCH);
        hgemm_split<false><<<grid, NTHREADS, SMEM_TOTAL>>>(
            ahi, alo, N_NODES,
            hhi, hlo, M_ALL, (long)N_NODES,
            nullptr, nullptr, out, D_OUT, (long)(N_NODES * D_OUT),
            N_NODES);
    }
}

// round 6
// speedup vs baseline: 4.6727x; 2.1219x over previous
#include <cuda_runtime.h>
#include <cuda_fp16.h>
#include <cstdint>

// ---------------------------------------------------------------------------
// GCN via mma.sync fp16 GEMMs (fp32 accumulate). Single MMA per product:
// fp16 input rounding gives norm rel_err ~2.5e-4 << 1e-3 threshold.
//   GEMM1: H^T[256][32768] = W^T @ X^T  (A=W^T K-major, B=X K-major) -> fp16
//   GEMM2: Out[b] = adj @ H_b           (A=adj K-major, B=H^T K-major) -> fp32
// R6: 4-stage cp.async ring, 1 syncthreads/stage, 2 CTAs/SM.
// ---------------------------------------------------------------------------

#define N_NODES 512
#define N_BATCH 64
#define D_IN    256
#define D_OUT   256
#define M_ALL   (N_NODES * N_BATCH)   // 32768

#define BM 128
#define BN 128
#define BKB 32                        // fp16 k per stage
#define NTHREADS 256
#define S_STAGES 4
#define PITCHB 80                     // smem row pitch bytes (32 halves + pad)
#define TILEB (128 * PITCHB)          // 10240 per matrix
#define STAGEB (2 * TILEB)            // A + B
#define SMEM_TOTAL (S_STAGES * STAGEB)  // 81920
#define OFF_A 0
#define OFF_B TILEB

// device scratch
__device__ __half g_xh[(size_t)M_ALL * D_IN];
__device__ __half g_wth[D_OUT * D_IN];
__device__ __half g_adjh[N_NODES * N_NODES];
__device__ __half g_h[(size_t)D_OUT * M_ALL];

// ---------------- helpers ----------------
__device__ __forceinline__ uint32_t smem_u32(const void* p) {
    uint32_t a;
    asm("{ .reg .u64 t; cvta.to.shared.u64 t, %1; cvt.u32.u64 %0, t; }" : "=r"(a) : "l"(p));
    return a;
}
__device__ __forceinline__ void cp16(uint32_t dst, const void* src) {
    asm volatile("cp.async.cg.shared.global [%0], [%1], 16;" :: "r"(dst), "l"(src) : "memory");
}
__device__ __forceinline__ void cp_commit() {
    asm volatile("cp.async.commit_group;" ::: "memory");
}
template <int N>
__device__ __forceinline__ void cp_wait() {
    asm volatile("cp.async.wait_group %0;" :: "n"(N) : "memory");
}
__device__ __forceinline__ void ldsm_x4(uint32_t* r, uint32_t addr) {
    asm volatile("ldmatrix.sync.aligned.m8n8.x4.shared.b16 {%0,%1,%2,%3}, [%4];"
                 : "=r"(r[0]), "=r"(r[1]), "=r"(r[2]), "=r"(r[3]) : "r"(addr));
}
__device__ __forceinline__ void mma_f16(float* c, const uint32_t* a, const uint32_t* b) {
    asm volatile(
        "mma.sync.aligned.m16n8k16.row.col.f32.f16.f16.f32 "
        "{%0,%1,%2,%3}, {%4,%5,%6,%7}, {%8,%9}, {%0,%1,%2,%3};"
        : "+f"(c[0]), "+f"(c[1]), "+f"(c[2]), "+f"(c[3])
        : "r"(a[0]), "r"(a[1]), "r"(a[2]), "r"(a[3]), "r"(b[0]), "r"(b[1]));
}

// ---------------- convert kernels ----------------
__global__ __launch_bounds__(256) void cvt8(const float* __restrict__ in,
                                            __half* __restrict__ out, int n8) {
    int i = blockIdx.x * blockDim.x + threadIdx.x;
    int stride = gridDim.x * blockDim.x;
    for (; i < n8; i += stride) {
        float4 a = ((const float4*)in)[2 * i];
        float4 b = ((const float4*)in)[2 * i + 1];
        __half2 h0 = __float22half2_rn(make_float2(a.x, a.y));
        __half2 h1 = __float22half2_rn(make_float2(a.z, a.w));
        __half2 h2 = __float22half2_rn(make_float2(b.x, b.y));
        __half2 h3 = __float22half2_rn(make_float2(b.z, b.w));
        uint4 v = {*(uint32_t*)&h0, *(uint32_t*)&h1, *(uint32_t*)&h2, *(uint32_t*)&h3};
        ((uint4*)out)[i] = v;
    }
}

__global__ __launch_bounds__(256) void cvt_wt(const float* __restrict__ w,
                                              __half* __restrict__ wt) {
    int o = blockIdx.x;
    int i = threadIdx.x;
    wt[o * D_IN + i] = __float2half_rn(w[i * D_OUT + o]);
}

// ---------------- main GEMM: C = A * B^T (both K-major, fp16) ----------------
template <bool HALF_OUT>
__global__ __launch_bounds__(NTHREADS, 2)
void hgemm_f16(const __half* __restrict__ A, int lda,
               const __half* __restrict__ B, int ldb, long bStride,
               __half* __restrict__ Ch, float* __restrict__ Cf,
               int ldc, long cStride, int K) {
    extern __shared__ char smem[];
    const uint32_t sb = smem_u32(smem);
    const int tid = threadIdx.x;
    const int lane = tid & 31;
    const int wid = tid >> 5;
    const int wm = (wid & 3) * 32;   // warp m offset
    const int wn = (wid >> 2) * 64;  // warp n offset

    const int m0 = blockIdx.y * BM;
    const int n0 = blockIdx.x * BN;
    const long bz = blockIdx.z;
    B += bz * bStride;

    // cp.async coords: rows lr, lr+64; 16B chunk c = tid&3
    const int lr = tid >> 2;
    const int lcH = (tid & 3) * 8;               // halves
    const uint32_t soBase = (uint32_t)((tid & 3) * 16);

    // ldmatrix addresses
    const uint32_t aOff = (uint32_t)((wm + (lane & 15)) * PITCHB + ((lane >> 4) << 4));
    const uint32_t bOff = (uint32_t)((wn + ((lane >> 4) << 3) + (lane & 7)) * PITCHB +
                                     (((lane >> 3) & 1) << 4));

    float acc[2][8][4];
#pragma unroll
    for (int mt = 0; mt < 2; mt++)
#pragma unroll
        for (int nt = 0; nt < 8; nt++)
#pragma unroll
            for (int q = 0; q < 4; q++) acc[mt][nt][q] = 0.0f;

    const int NT = K / BKB;

    auto load_stage = [&](int t) {
        const uint32_t st = sb + (uint32_t)((t & (S_STAGES - 1)) * STAGEB);
        const int k0 = t * BKB + lcH;
#pragma unroll
        for (int j = 0; j < 2; j++) {
            int r = lr + j * 64;
            uint32_t so = (uint32_t)(r * PITCHB) + soBase;
            cp16(st + OFF_A + so, A + (size_t)(m0 + r) * lda + k0);
            cp16(st + OFF_B + so, B + (size_t)(n0 + r) * ldb + k0);
        }
    };

    // prologue: stages 0..S-2
#pragma unroll
    for (int s = 0; s < S_STAGES - 1; s++) {
        load_stage(s);
        cp_commit();
    }

    for (int t = 0; t < NT; t++) {
        cp_wait<S_STAGES - 2>();
        __syncthreads();

        const uint32_t st = sb + (uint32_t)((t & (S_STAGES - 1)) * STAGEB);
#pragma unroll
        for (int ko = 0; ko < 2; ko++) {
            uint32_t ah[2][4];
#pragma unroll
            for (int mt = 0; mt < 2; mt++)
                ldsm_x4(ah[mt], st + OFF_A + aOff + mt * 16 * PITCHB + ko * 32);
#pragma unroll
            for (int np = 0; np < 4; np++) {
                uint32_t bh[4];
                ldsm_x4(bh, st + OFF_B + bOff + np * 16 * PITCHB + ko * 32);
#pragma unroll
                for (int sub = 0; sub < 2; sub++)
#pragma unroll
                    for (int mt = 0; mt < 2; mt++)
                        mma_f16(acc[mt][np * 2 + sub], ah[mt], bh + sub * 2);
            }
        }

        if (t + S_STAGES - 1 < NT) load_stage(t + S_STAGES - 1);
        cp_commit();
    }

    // epilogue
    const int l4 = lane >> 2;
    const int lp = lane & 3;
#pragma unroll
    for (int mt = 0; mt < 2; mt++) {
#pragma unroll
        for (int nt = 0; nt < 8; nt++) {
            const float* c = acc[mt][nt];
            long m = m0 + wm + mt * 16 + l4;
            long n = n0 + wn + nt * 8 + lp * 2;
            if (HALF_OUT) {
                __half2 p0 = __float22half2_rn(make_float2(c[0], c[1]));
                __half2 p1 = __float22half2_rn(make_float2(c[2], c[3]));
                *(uint32_t*)(Ch + m * ldc + n) = *(uint32_t*)&p0;
                *(uint32_t*)(Ch + (m + 8) * ldc + n) = *(uint32_t*)&p1;
            } else {
                float* base = Cf + bz * cStride;
                *(float2*)(base + m * ldc + n) = make_float2(c[0], c[1]);
                *(float2*)(base + (m + 8) * ldc + n) = make_float2(c[2], c[3]);
            }
        }
    }
}

// ---------------- launch ----------------
extern "C" void kernel_launch(void* const* d_in, const int* in_sizes, int n_in,
                              void* d_out, int out_size) {
    const float* x      = (const float*)d_in[0];
    const float* weight = (const float*)d_in[2];
    const float* adj    = (const float*)d_in[3];
    float* out          = (float*)d_out;

    __half *xh, *wth, *adjh, *h;
    cudaGetSymbolAddress((void**)&xh, g_xh);
    cudaGetSymbolAddress((void**)&wth, g_wth);
    cudaGetSymbolAddress((void**)&adjh, g_adjh);
    cudaGetSymbolAddress((void**)&h, g_h);

    cudaFuncSetAttribute(hgemm_f16<true>, cudaFuncAttributeMaxDynamicSharedMemorySize, SMEM_TOTAL);
    cudaFuncSetAttribute(hgemm_f16<false>, cudaFuncAttributeMaxDynamicSharedMemorySize, SMEM_TOTAL);

    // converts
    cvt8<<<1024, 256>>>(x, xh, M_ALL * D_IN / 8);
    cvt8<<<128, 256>>>(adj, adjh, N_NODES * N_NODES / 8);
    cvt_wt<<<D_OUT, 256>>>(weight, wth);

    // GEMM1: H^T = W^T @ X^T ; A=W^T [256][256], B=X [32768][256] -> H^T fp16
    {
        dim3 grid(M_ALL / BN, D_OUT / BM, 1);
        hgemm_f16<true><<<grid, NTHREADS, SMEM_TOTAL>>>(
            wth, D_IN,
            xh, D_IN, 0L,
            h, nullptr, M_ALL, 0L,
            D_IN);
    }
    // GEMM2: Out[b] = adj @ H_b ; A=adj [512][512], B=H^T col-slice b*512
    {
        dim3 grid(D_OUT / BN, N_NODES / BM, N_BATCH);
        hgemm_f16<false><<<grid, NTHREADS, SMEM_TOTAL>>>(
            adjh, N_NODES,
            h, M_ALL, (long)N_NODES,
            nullptr, out, D_OUT, (long)(N_NODES * D_OUT),
            N_NODES);
    }
}

// round 8
// speedup vs baseline: 5.2895x; 1.1320x over previous
#include <cuda_runtime.h>
#include <cuda_fp16.h>
#include <cstdint>

// ---------------------------------------------------------------------------
// GCN via mma.sync fp16 GEMMs (fp32 accumulate).
//   GEMM1: H^T[256][32768] = W^T @ X^T  -> fp16
//   GEMM2: Out[b] = adj @ H_b           -> fp32
// R8: R7 + fix cp.async tail race (unconditional commit keeps wait_group<1>
//     semantics aligned with stage indices).
// ---------------------------------------------------------------------------

#define N_NODES 512
#define N_BATCH 64
#define D_IN    256
#define D_OUT   256
#define M_ALL   (N_NODES * N_BATCH)   // 32768

#define BM 128
#define BN 128
#define BKB 64                        // fp16 k per stage
#define NTHREADS 256
#define S_STAGES 3
#define PITCHB 144                    // 128B row + 16B pad -> ldsm conflict-free
#define TILEB (128 * PITCHB)          // 18432 per matrix
#define STAGEB (2 * TILEB)            // 36864
#define SMEM_TOTAL (S_STAGES * STAGEB) // 110592
#define OFF_A 0
#define OFF_B TILEB

// device scratch
__device__ __half g_xh[(size_t)M_ALL * D_IN];
__device__ __half g_wth[D_OUT * D_IN];
__device__ __half g_adjh[N_NODES * N_NODES];
__device__ __half g_h[(size_t)D_OUT * M_ALL];

// ---------------- helpers ----------------
__device__ __forceinline__ uint32_t smem_u32(const void* p) {
    uint32_t a;
    asm("{ .reg .u64 t; cvta.to.shared.u64 t, %1; cvt.u32.u64 %0, t; }" : "=r"(a) : "l"(p));
    return a;
}
__device__ __forceinline__ void cp16(uint32_t dst, const void* src) {
    asm volatile("cp.async.cg.shared.global [%0], [%1], 16;" :: "r"(dst), "l"(src) : "memory");
}
__device__ __forceinline__ void cp_commit() {
    asm volatile("cp.async.commit_group;" ::: "memory");
}
template <int N>
__device__ __forceinline__ void cp_wait() {
    asm volatile("cp.async.wait_group %0;" :: "n"(N) : "memory");
}
__device__ __forceinline__ void ldsm_x4(uint32_t* r, uint32_t addr) {
    asm volatile("ldmatrix.sync.aligned.m8n8.x4.shared.b16 {%0,%1,%2,%3}, [%4];"
                 : "=r"(r[0]), "=r"(r[1]), "=r"(r[2]), "=r"(r[3]) : "r"(addr));
}
__device__ __forceinline__ void mma_f16(float* c, const uint32_t* a, const uint32_t* b) {
    asm volatile(
        "mma.sync.aligned.m16n8k16.row.col.f32.f16.f16.f32 "
        "{%0,%1,%2,%3}, {%4,%5,%6,%7}, {%8,%9}, {%0,%1,%2,%3};"
        : "+f"(c[0]), "+f"(c[1]), "+f"(c[2]), "+f"(c[3])
        : "r"(a[0]), "r"(a[1]), "r"(a[2]), "r"(a[3]), "r"(b[0]), "r"(b[1]));
}

// ---------------- merged convert kernel ----------------
// blocks [0,512): x cvt | [512,528): adj cvt | [528,784): w transpose cvt
__global__ __launch_bounds__(256) void cvt_all(const float* __restrict__ x,
                                               const float* __restrict__ adj,
                                               const float* __restrict__ w,
                                               __half* __restrict__ xh,
                                               __half* __restrict__ adjh,
                                               __half* __restrict__ wth) {
    const int b = blockIdx.x;
    if (b < 512) {
        const int n8 = M_ALL * D_IN / 8;   // 1048576
        int i = b * 256 + threadIdx.x;
        const int stride = 512 * 256;
        for (; i < n8; i += stride) {
            float4 a = ((const float4*)x)[2 * i];
            float4 c = ((const float4*)x)[2 * i + 1];
            __half2 h0 = __float22half2_rn(make_float2(a.x, a.y));
            __half2 h1 = __float22half2_rn(make_float2(a.z, a.w));
            __half2 h2 = __float22half2_rn(make_float2(c.x, c.y));
            __half2 h3 = __float22half2_rn(make_float2(c.z, c.w));
            uint4 v = {*(uint32_t*)&h0, *(uint32_t*)&h1, *(uint32_t*)&h2, *(uint32_t*)&h3};
            ((uint4*)xh)[i] = v;
        }
    } else if (b < 528) {
        const int n8 = N_NODES * N_NODES / 8;  // 32768
        int i = (b - 512) * 256 + threadIdx.x;
        const int stride = 16 * 256;
        for (; i < n8; i += stride) {
            float4 a = ((const float4*)adj)[2 * i];
            float4 c = ((const float4*)adj)[2 * i + 1];
            __half2 h0 = __float22half2_rn(make_float2(a.x, a.y));
            __half2 h1 = __float22half2_rn(make_float2(a.z, a.w));
            __half2 h2 = __float22half2_rn(make_float2(c.x, c.y));
            __half2 h3 = __float22half2_rn(make_float2(c.z, c.w));
            uint4 v = {*(uint32_t*)&h0, *(uint32_t*)&h1, *(uint32_t*)&h2, *(uint32_t*)&h3};
            ((uint4*)adjh)[i] = v;
        }
    } else {
        int o = b - 528;            // 0..255
        int i = threadIdx.x;        // 0..255
        wth[o * D_IN + i] = __float2half_rn(w[i * D_OUT + o]);
    }
}

// ---------------- main GEMM: C = A * B^T (both K-major, fp16) ----------------
template <bool HALF_OUT>
__global__ __launch_bounds__(NTHREADS, 2)
void hgemm_f16(const __half* __restrict__ A, int lda,
               const __half* __restrict__ B, int ldb, long bStride,
               __half* __restrict__ Ch, float* __restrict__ Cf,
               int ldc, long cStride, int K) {
    extern __shared__ char smem[];
    const uint32_t sb = smem_u32(smem);
    const int tid = threadIdx.x;
    const int lane = tid & 31;
    const int wid = tid >> 5;
    const int wm = (wid & 3) * 32;   // warp m offset
    const int wn = (wid >> 2) * 64;  // warp n offset

    const int m0 = blockIdx.y * BM;
    const int n0 = blockIdx.x * BN;
    const long bz = blockIdx.z;
    B += bz * bStride;

    // cp.async coords: per matrix 128 rows x 8 chunks of 16B; 4 chunks/thread
    const int cr = tid >> 3;          // base row 0..31 (+32 per j)
    const int cc = tid & 7;           // 16B chunk in row
    const uint32_t soBase = (uint32_t)(cc * 16);
    const int gcol = cc * 8;          // halves

    // ldmatrix addresses (conflict-free: PITCHB mod 128 = 16)
    const uint32_t aOff = (uint32_t)((wm + (lane & 15)) * PITCHB + ((lane >> 4) << 4));
    const uint32_t bOff = (uint32_t)((wn + ((lane >> 4) << 3) + (lane & 7)) * PITCHB +
                                     (((lane >> 3) & 1) << 4));

    float acc[2][8][4];
#pragma unroll
    for (int mt = 0; mt < 2; mt++)
#pragma unroll
        for (int nt = 0; nt < 8; nt++)
#pragma unroll
            for (int q = 0; q < 4; q++) acc[mt][nt][q] = 0.0f;

    const int NT = K / BKB;

    auto load_stage = [&](int t) {
        const uint32_t st = sb + (uint32_t)((t % S_STAGES) * STAGEB);
        const int k0 = t * BKB + gcol;
#pragma unroll
        for (int j = 0; j < 4; j++) {
            int r = cr + j * 32;
            uint32_t so = (uint32_t)(r * PITCHB) + soBase;
            cp16(st + OFF_A + so, A + (size_t)(m0 + r) * lda + k0);
            cp16(st + OFF_B + so, B + (size_t)(n0 + r) * ldb + k0);
        }
        cp_commit();
    };

    load_stage(0);
    if (NT > 1) load_stage(1);

    for (int t = 0; t < NT; t++) {
        cp_wait<1>();
        __syncthreads();

        const uint32_t st = sb + (uint32_t)((t % S_STAGES) * STAGEB);

        // A-frag double buffer across ko
        uint32_t ah[2][2][4];
#pragma unroll
        for (int mt = 0; mt < 2; mt++)
            ldsm_x4(ah[0][mt], st + OFF_A + aOff + mt * 16 * PITCHB);

#pragma unroll
        for (int ko = 0; ko < 4; ko++) {
            const int cur = ko & 1, nxt = cur ^ 1;
            if (ko < 3) {
#pragma unroll
                for (int mt = 0; mt < 2; mt++)
                    ldsm_x4(ah[nxt][mt], st + OFF_A + aOff + mt * 16 * PITCHB + (ko + 1) * 32);
            }
#pragma unroll
            for (int np = 0; np < 4; np++) {
                uint32_t bh[4];
                ldsm_x4(bh, st + OFF_B + bOff + np * 16 * PITCHB + ko * 32);
#pragma unroll
                for (int sub = 0; sub < 2; sub++)
#pragma unroll
                    for (int mt = 0; mt < 2; mt++)
                        mma_f16(acc[mt][np * 2 + sub], ah[cur][mt], bh + sub * 2);
            }
        }

        __syncthreads();
        // Commit EVERY iteration (empty group when nothing to load) so that
        // cp_wait<1> at iteration t always implies stage t is complete.
        if (t + 2 < NT) {
            load_stage(t + 2);
        } else {
            cp_commit();
        }
    }

    // epilogue
    const int l4 = lane >> 2;
    const int lp = lane & 3;
#pragma unroll
    for (int mt = 0; mt < 2; mt++) {
#pragma unroll
        for (int nt = 0; nt < 8; nt++) {
            const float* c = acc[mt][nt];
            long m = m0 + wm + mt * 16 + l4;
            long n = n0 + wn + nt * 8 + lp * 2;
            if (HALF_OUT) {
                __half2 p0 = __float22half2_rn(make_float2(c[0], c[1]));
                __half2 p1 = __float22half2_rn(make_float2(c[2], c[3]));
                *(uint32_t*)(Ch + m * ldc + n) = *(uint32_t*)&p0;
                *(uint32_t*)(Ch + (m + 8) * ldc + n) = *(uint32_t*)&p1;
            } else {
                float* base = Cf + bz * cStride;
                *(float2*)(base + m * ldc + n) = make_float2(c[0], c[1]);
                *(float2*)(base + (m + 8) * ldc + n) = make_float2(c[2], c[3]);
            }
        }
    }
}

// ---------------- launch ----------------
extern "C" void kernel_launch(void* const* d_in, const int* in_sizes, int n_in,
                              void* d_out, int out_size) {
    const float* x      = (const float*)d_in[0];
    const float* weight = (const float*)d_in[2];
    const float* adj    = (const float*)d_in[3];
    float* out          = (float*)d_out;

    __half *xh, *wth, *adjh, *h;
    cudaGetSymbolAddress((void**)&xh, g_xh);
    cudaGetSymbolAddress((void**)&wth, g_wth);
    cudaGetSymbolAddress((void**)&adjh, g_adjh);
    cudaGetSymbolAddress((void**)&h, g_h);

    cudaFuncSetAttribute(hgemm_f16<true>, cudaFuncAttributeMaxDynamicSharedMemorySize, SMEM_TOTAL);
    cudaFuncSetAttribute(hgemm_f16<false>, cudaFuncAttributeMaxDynamicSharedMemorySize, SMEM_TOTAL);

    cvt_all<<<784, 256>>>(x, adj, weight, xh, adjh, wth);

    // GEMM1: H^T = W^T @ X^T ; A=W^T [256][256], B=X [32768][256] -> H^T fp16
    {
        dim3 grid(M_ALL / BN, D_OUT / BM, 1);
        hgemm_f16<true><<<grid, NTHREADS, SMEM_TOTAL>>>(
            wth, D_IN,
            xh, D_IN, 0L,
            h, nullptr, M_ALL, 0L,
            D_IN);
    }
    // GEMM2: Out[b] = adj @ H_b ; A=adj [512][512], B=H^T col-slice b*512
    {
        dim3 grid(D_OUT / BN, N_NODES / BM, N_BATCH);
        hgemm_f16<false><<<grid, NTHREADS, SMEM_TOTAL>>>(
            adjh, N_NODES,
            h, M_ALL, (long)N_NODES,
            nullptr, out, D_OUT, (long)(N_NODES * D_OUT),
            N_NODES);
    }
}